// round 17
// baseline (speedup 1.0000x reference)
#include <cuda_runtime.h>
#include <cuda_fp16.h>
#include <cstdint>

#define SNU 72        // nf/wt_k/wt_v u32 stride (144 halves), XOR-4 swizzled
#define SNH 144
#define SLU 66        // wt_l/wt_q/x1h u32 stride (132 halves)
#define SLH 132

// smem byte offsets
#define OFF_WK  0              // 36864
#define OFF_WV  36864          // 36864
#define OFF_WL  73728          // 33792
#define OFF_WQ  107520         // 33792
#define OFF_NF  141312         // 2 groups x 18432 (64 rows each)
#define OFF_X1H 178176         // 2 x 2112 (8 rows, rows 4..7 stay zero)
#define OFF_QO  182400         // 2 x 2048
#define OFF_X1F 186496         // 2 x 2048
#define OFF_YB  190592         // 2 x 2048
#define OFF_CB  194688         // 3072
#define SMEM_TOT 197760

#define BARS(id) asm volatile("bar.sync %0, 128;" :: "r"(id) : "memory")

__device__ __forceinline__ void mma16816(float* d, const unsigned* a, unsigned b0, unsigned b1) {
    asm volatile(
        "mma.sync.aligned.m16n8k16.row.col.f32.f16.f16.f32 "
        "{%0,%1,%2,%3}, {%4,%5,%6,%7}, {%8,%9}, {%0,%1,%2,%3};\n"
        : "+f"(d[0]), "+f"(d[1]), "+f"(d[2]), "+f"(d[3])
        : "r"(a[0]), "r"(a[1]), "r"(a[2]), "r"(a[3]), "r"(b0), "r"(b1));
}

// warp lw of a group: rows lw*16..+15 of the group's 64-row nf, both K and V.
__device__ __forceinline__ void gemm_regs(const char* sm, const char* nfG,
                                          float (&aK)[16][4], float (&aV)[16][4],
                                          int lw, int gid, int tig) {
    const unsigned* nfU = (const unsigned*)nfG;
    const unsigned* wkU = (const unsigned*)(sm + OFF_WK);
    const unsigned* wvU = (const unsigned*)(sm + OFF_WV);
    int sw = ((gid >> 2) & 1) * 4;
#pragma unroll
    for (int i = 0; i < 16; i++)
#pragma unroll
        for (int l = 0; l < 4; l++) { aK[i][l] = 0.f; aV[i][l] = 0.f; }
    for (int ch = 0; ch < 9; ch++) {
        int kr = ch * 8 + tig;
        int kc = kr ^ sw, kc4 = (kr + 4) ^ sw;
        const unsigned* p0 = nfU + (lw * 16 + gid) * SNU;
        const unsigned* p1 = p0 + 8 * SNU;
        unsigned A[4] = {p0[kc], p1[kc], p0[kc4], p1[kc4]};
#pragma unroll
        for (int nt = 0; nt < 16; nt++) {
            const unsigned* pk = wkU + (nt * 8 + gid) * SNU;
            mma16816(aK[nt], A, pk[kc], pk[kc4]);
            const unsigned* pv = wvU + (nt * 8 + gid) * SNU;
            mma16816(aV[nt], A, pv[kc], pv[kc4]);
        }
    }
}

// one warp normalizes one 128-float smem row in place
__device__ __forceinline__ void layernorm_row(float* v, const float* g, const float* b, int lane) {
    float4 val = ((float4*)v)[lane];
    float s = val.x + val.y + val.z + val.w;
    float s2 = val.x * val.x + val.y * val.y + val.z * val.z + val.w * val.w;
#pragma unroll
    for (int o = 16; o; o >>= 1) {
        s  += __shfl_xor_sync(0xffffffffu, s, o);
        s2 += __shfl_xor_sync(0xffffffffu, s2, o);
    }
    float m = s * (1.f / 128.f);
    float inv = rsqrtf(s2 * (1.f / 128.f) - m * m + 1e-5f);
    int c = lane * 4;
    float o0 = (val.x - m) * inv * g[c] + b[c];
    float o1 = (val.y - m) * inv * g[c + 1] + b[c + 1];
    float o2 = (val.z - m) * inv * g[c + 2] + b[c + 2];
    float o3 = (val.w - m) * inv * g[c + 3] + b[c + 3];
    ((float4*)v)[lane] = make_float4(o0, o1, o2, o3);
}

__global__ void __launch_bounds__(256, 1)
tb_main(const float* __restrict__ x,
        const float* __restrict__ knn, const float* __restrict__ xyz,
        const float* __restrict__ q_w, const float* __restrict__ q_b,
        const float* __restrict__ k_w, const float* __restrict__ k_b,
        const float* __restrict__ v_w, const float* __restrict__ v_b,
        const float* __restrict__ lin_w, const float* __restrict__ lin_b,
        const float* __restrict__ l1g, const float* __restrict__ l1b,
        const float* __restrict__ l2g, const float* __restrict__ l2b,
        float* __restrict__ out, int n)
{
    extern __shared__ __align__(16) char sm[];
    int tid = threadIdx.x;
    int w8 = tid >> 5, lane = tid & 31, gid = lane >> 2, tig = lane & 3;
    float* cb = (float*)(sm + OFF_CB);

    // zero everything below CB (weight/nf padding + x1h zero rows)
    {
        float4 z4 = make_float4(0.f, 0.f, 0.f, 0.f);
        for (int i = tid; i < OFF_CB / 16; i += 256) ((float4*)sm)[i] = z4;
    }
    __syncthreads();
    // weights transposed; K/V bias folded as weight row 131 (nf col 131 == 1.0)
    for (int i = tid; i < 132 * 128; i += 256) {
        int j = i >> 7, c = i & 127;
        int swh = ((c >> 2) & 1) * 8;
        float fk = (j < 131) ? k_w[j * 128 + c] : k_b[c];
        float fv = (j < 131) ? v_w[j * 128 + c] : v_b[c];
        ((half*)(sm + OFF_WK))[c * SNH + (j ^ swh)] = __float2half(fk);
        ((half*)(sm + OFF_WV))[c * SNH + (j ^ swh)] = __float2half(fv);
        if (j < 128) {
            ((half*)(sm + OFF_WL))[c * SLH + j] = __float2half(lin_w[i]);
            ((half*)(sm + OFF_WQ))[c * SLH + j] = __float2half(q_w[i]);
        }
    }
    if (tid < 128) {
        cb[tid]       = lin_b[tid]; cb[128 + tid] = l1g[tid];
        cb[256 + tid] = l1b[tid];   cb[384 + tid] = l2g[tid];
        cb[512 + tid] = l2b[tid];   cb[640 + tid] = q_b[tid];
        // bias-one column (131) for both group nf buffers, init-only
        int gg = tid >> 6, r = tid & 63;
        half* nf = (half*)(sm + OFF_NF + gg * 18432);
        int swh = ((r >> 2) & 1) * 8;
        nf[r * SNH + (131 ^ swh)] = __float2half(1.0f);
    }
    const float *lb = cb, *g1 = cb + 128, *b1 = cb + 256;
    const float *g2 = cb + 384, *b2 = cb + 512, *qb = cb + 640;

    // group split: one warp per SMSP per group; groups fully independent
    int g  = w8 >> 2, lw = w8 & 3;
    char*  nfG  = sm + OFF_NF + g * 18432;
    half*  x1hG = (half*)(sm + OFF_X1H + g * 2112);
    float* qoG  = (float*)(sm + OFF_QO  + g * 2048);
    float* x1fG = (float*)(sm + OFF_X1F + g * 2048);
    float* ybG  = (float*)(sm + OFF_YB  + g * 2048);
    int B1 = g * 4 + 1, B2 = g * 4 + 2, B3 = g * 4 + 3, B4 = g * 4 + 4;

    int nblk4 = (n + 3) >> 2;
    int n16 = n * 16;
    int WSTR = gridDim.x * 2;
    int blk0 = blockIdx.x * 2 + g;
    const float4* knn4 = (const float4*)knn;
    const float4* x4 = (const float4*)x;
    const float inv_d = 0.08838834764831845f;  // 1/sqrt(128)

    int rLoc = lw * 16 + (lane >> 1);          // this warp's nf row for drains
    int sw4  = ((rLoc >> 2) & 1) * 4;

    // ---- prologue: nf(blk0) warp-private, stage x ----
    if (blk0 < nblk4) {
        unsigned* nfU = (unsigned*)nfG;
        int src = min(blk0 * 64 + rLoc, n16 - 1);
#pragma unroll
        for (int k = 0; k < 16; k++) {
            int col4 = (lane & 1) * 16 + k;
            float4 v = knn4[(size_t)src * 32 + col4];
            half2* d = (half2*)(nfU + rLoc * SNU + ((col4 * 2) ^ sw4));
            d[0] = __floats2half2_rn(v.x, v.y);
            d[1] = __floats2half2_rn(v.z, v.w);
        }
        if (lane < 16) {
            int r2 = lw * 16 + lane;
            int s2 = min(blk0 * 64 + r2, n16 - 1);
            int swh = ((r2 >> 2) & 1) * 8;
            half* nf = (half*)nfG;
            nf[r2 * SNH + (128 ^ swh)] = __float2half(xyz[s2 * 3 + 0]);
            nf[r2 * SNH + (129 ^ swh)] = __float2half(xyz[s2 * 3 + 1]);
            nf[r2 * SNH + (130 ^ swh)] = __float2half(xyz[s2 * 3 + 2]);
        }
        int np = min(blk0 * 4 + lw, n - 1);
        float4 v = x4[np * 32 + lane];
        ((float4*)x1fG)[lw * 32 + lane] = v;
        half2* d = (half2*)(x1hG + lw * SLH + lane * 4);
        d[0] = __floats2half2_rn(v.x, v.y);
        d[1] = __floats2half2_rn(v.z, v.w);
    }
    __syncthreads();

    float aK[16][4], aV[16][4];

    for (int blk = blk0; blk < nblk4; blk += WSTR) {
        int nb = blk + WSTR;
        bool h1 = nb < nblk4;

        // early LDG: next nf (first half) + next x
        float4 pfA[8], px;
        if (h1) {
            int src = min(nb * 64 + rLoc, n16 - 1);
#pragma unroll
            for (int k = 0; k < 8; k++)
                pfA[k] = knn4[(size_t)src * 32 + (lane & 1) * 16 + k];
            int np = min(nb * 4 + lw, n - 1);
            px = x4[np * 32 + lane];
        }

        // ---- Q gemm: warp lw -> cols lw*32..+31, rows = points 0..3 ----
        {
            int c0 = lw * 32;
            float acc[4][4];
#pragma unroll
            for (int i = 0; i < 4; i++)
#pragma unroll
                for (int l = 0; l < 4; l++) acc[i][l] = 0.f;
            for (int ch = 0; ch < 8; ch++) {
                int kc = ch * 8 + tig;
                const unsigned* p0 = (const unsigned*)x1hG + gid * SLU;
                unsigned a[4] = {p0[kc], 0u, p0[kc + 4], 0u};
#pragma unroll
                for (int nt = 0; nt < 4; nt++) {
                    const unsigned* pb = (const unsigned*)(sm + OFF_WQ) + (c0 + nt * 8 + gid) * SLU;
                    mma16816(acc[nt], a, pb[kc], pb[kc + 4]);
                }
            }
            if (gid < 4) {
#pragma unroll
                for (int nt = 0; nt < 4; nt++) {
                    int c = c0 + nt * 8 + 2 * tig;
                    qoG[gid * 128 + c]     = acc[nt][0] + qb[c];
                    qoG[gid * 128 + c + 1] = acc[nt][1] + qb[c + 1];
                }
            }
        }
        BARS(B1);   // qoG ready

        gemm_regs(sm, nfG, aK, aV, lw, gid, tig);

        // drain A (own rows), issue B + xyz loads
        float4 pfB[8];
        float xz0 = 0.f, xz1 = 0.f, xz2 = 0.f;
        if (h1) {
            unsigned* nfU = (unsigned*)nfG;
#pragma unroll
            for (int k = 0; k < 8; k++) {
                int col4 = (lane & 1) * 16 + k;
                half2* d = (half2*)(nfU + rLoc * SNU + ((col4 * 2) ^ sw4));
                d[0] = __floats2half2_rn(pfA[k].x, pfA[k].y);
                d[1] = __floats2half2_rn(pfA[k].z, pfA[k].w);
            }
            int src = min(nb * 64 + rLoc, n16 - 1);
#pragma unroll
            for (int k = 0; k < 8; k++)
                pfB[k] = knn4[(size_t)src * 32 + (lane & 1) * 16 + 8 + k];
            if (lane < 16) {
                int s2 = min(nb * 64 + lw * 16 + lane, n16 - 1);
                xz0 = xyz[s2 * 3 + 0]; xz1 = xyz[s2 * 3 + 1]; xz2 = xyz[s2 * 3 + 2];
            }
        }

        // ---- register epilogue: this warp's point = blk*4 + lw ----
        {
            int h0 = gid >> 2;
            const float* qrow = qoG + lw * 128;
            const float* xrow = x1fG + lw * 128;
            float qv[2][4][2];
#pragma unroll
            for (int m = 0; m < 2; m++) {
                int h = h0 + 2 * m;
#pragma unroll
                for (int q3 = 0; q3 < 4; q3++) {
                    qv[m][q3][0] = qrow[h * 32 + q3 * 8 + 2 * tig];
                    qv[m][q3][1] = qrow[h * 32 + q3 * 8 + 2 * tig + 1];
                }
            }
            float S[2][4];
#pragma unroll
            for (int m = 0; m < 2; m++)
#pragma unroll
                for (int j = 0; j < 4; j++) S[m][j] = 0.f;
#pragma unroll
            for (int nt = 0; nt < 16; nt++) {
                int j = nt >> 2, q3 = nt & 3;
                S[0][j] = fmaf(aK[nt][0], qv[0][q3][0], fmaf(aK[nt][1], qv[0][q3][1], S[0][j]));
                S[1][j] = fmaf(aK[nt][2], qv[1][q3][0], fmaf(aK[nt][3], qv[1][q3][1], S[1][j]));
            }
#pragma unroll
            for (int m = 0; m < 2; m++)
#pragma unroll
                for (int j = 0; j < 4; j++) {
                    S[m][j] += __shfl_xor_sync(0xffffffffu, S[m][j], 1);
                    S[m][j] += __shfl_xor_sync(0xffffffffu, S[m][j], 2);
                }
            float a_[2][4];
#pragma unroll
            for (int m = 0; m < 2; m++) {
                float mx = fmaxf(fmaxf(S[m][0], S[m][1]), fmaxf(S[m][2], S[m][3]));
                mx = fmaxf(mx, __shfl_xor_sync(0xffffffffu, mx, 4));
                mx = fmaxf(mx, __shfl_xor_sync(0xffffffffu, mx, 8));
                float e0 = __expf((S[m][0] - mx) * inv_d);
                float e1 = __expf((S[m][1] - mx) * inv_d);
                float e2 = __expf((S[m][2] - mx) * inv_d);
                float e3 = __expf((S[m][3] - mx) * inv_d);
                float sl = e0 + e1 + e2 + e3;
                sl += __shfl_xor_sync(0xffffffffu, sl, 4);
                sl += __shfl_xor_sync(0xffffffffu, sl, 8);
                float r = 1.f / sl;
                a_[m][0] = e0 * r; a_[m][1] = e1 * r; a_[m][2] = e2 * r; a_[m][3] = e3 * r;
            }
            float F[2][4][2];
#pragma unroll
            for (int m = 0; m < 2; m++)
#pragma unroll
                for (int q3 = 0; q3 < 4; q3++) { F[m][q3][0] = 0.f; F[m][q3][1] = 0.f; }
#pragma unroll
            for (int nt = 0; nt < 16; nt++) {
                int j = nt >> 2, q3 = nt & 3;
                F[0][q3][0] = fmaf(a_[0][j], aV[nt][0], F[0][q3][0]);
                F[0][q3][1] = fmaf(a_[0][j], aV[nt][1], F[0][q3][1]);
                F[1][q3][0] = fmaf(a_[1][j], aV[nt][2], F[1][q3][0]);
                F[1][q3][1] = fmaf(a_[1][j], aV[nt][3], F[1][q3][1]);
            }
#pragma unroll
            for (int m = 0; m < 2; m++)
#pragma unroll
                for (int q3 = 0; q3 < 4; q3++)
#pragma unroll
                    for (int b = 0; b < 2; b++) {
                        F[m][q3][b] += __shfl_xor_sync(0xffffffffu, F[m][q3][b], 4);
                        F[m][q3][b] += __shfl_xor_sync(0xffffffffu, F[m][q3][b], 8);
                    }
            float xv[2][4][2], s1 = 0.f, sq = 0.f;
#pragma unroll
            for (int m = 0; m < 2; m++) {
                int h = h0 + 2 * m;
#pragma unroll
                for (int q3 = 0; q3 < 4; q3++)
#pragma unroll
                    for (int b = 0; b < 2; b++) {
                        float v = xrow[h * 32 + q3 * 8 + 2 * tig + b] + F[m][q3][b];
                        xv[m][q3][b] = v;
                        s1 += v; sq = fmaf(v, v, sq);
                    }
            }
#pragma unroll
            for (int o = 16; o; o >>= 1) {
                s1 += __shfl_xor_sync(0xffffffffu, s1, o);
                sq += __shfl_xor_sync(0xffffffffu, sq, o);
            }
            float mean = s1 * (1.f / 512.f);
            float inv = rsqrtf(sq * (1.f / 512.f) - mean * mean + 1e-5f);
            if ((gid & 3) == 0) {
#pragma unroll
                for (int m = 0; m < 2; m++) {
                    int h = h0 + 2 * m;
#pragma unroll
                    for (int q3 = 0; q3 < 4; q3++) {
                        int c = h * 32 + q3 * 8 + 2 * tig;
                        float o0 = (xv[m][q3][0] - mean) * inv * g1[c] + b1[c];
                        float o1 = (xv[m][q3][1] - mean) * inv * g1[c + 1] + b1[c + 1];
                        *(float2*)(x1fG + lw * 128 + c) = make_float2(o0, o1);
                        *(half2*)(x1hG + lw * SLH + c) = __floats2half2_rn(o0, o1);
                    }
                }
            }
        }
        BARS(B2);   // x1h/x1f (LN1) ready; qoG consumed

        // ---- lin gemm + combine: yb = lin(x1) + x1 + lin_b ----
        {
            int c0 = lw * 32;
            float acc[4][4];
#pragma unroll
            for (int i = 0; i < 4; i++)
#pragma unroll
                for (int l = 0; l < 4; l++) acc[i][l] = 0.f;
            for (int ch = 0; ch < 8; ch++) {
                int kc = ch * 8 + tig;
                const unsigned* p0 = (const unsigned*)x1hG + gid * SLU;
                unsigned a[4] = {p0[kc], 0u, p0[kc + 4], 0u};
#pragma unroll
                for (int nt = 0; nt < 4; nt++) {
                    const unsigned* pb = (const unsigned*)(sm + OFF_WL) + (c0 + nt * 8 + gid) * SLU;
                    mma16816(acc[nt], a, pb[kc], pb[kc + 4]);
                }
            }
            if (gid < 4) {
#pragma unroll
                for (int nt = 0; nt < 4; nt++) {
                    int c = c0 + nt * 8 + 2 * tig;
                    ybG[gid * 128 + c]     = acc[nt][0] + x1fG[gid * 128 + c]     + lb[c];
                    ybG[gid * 128 + c + 1] = acc[nt][1] + x1fG[gid * 128 + c + 1] + lb[c + 1];
                }
            }
        }
        // drain B + xyz -> own nf rows (warp-private; must precede next gemm only)
        if (h1) {
            unsigned* nfU = (unsigned*)nfG;
#pragma unroll
            for (int k = 0; k < 8; k++) {
                int col4 = (lane & 1) * 16 + 8 + k;
                half2* d = (half2*)(nfU + rLoc * SNU + ((col4 * 2) ^ sw4));
                d[0] = __floats2half2_rn(pfB[k].x, pfB[k].y);
                d[1] = __floats2half2_rn(pfB[k].z, pfB[k].w);
            }
            if (lane < 16) {
                int r2 = lw * 16 + lane;
                int swh = ((r2 >> 2) & 1) * 8;
                half* nf = (half*)nfG;
                nf[r2 * SNH + (128 ^ swh)] = __float2half(xz0);
                nf[r2 * SNH + (129 ^ swh)] = __float2half(xz1);
                nf[r2 * SNH + (130 ^ swh)] = __float2half(xz2);
            }
        }
        BARS(B3);   // yb ready; x1h consumed

        // LN2 + store (warp owns its point's row)
        layernorm_row(ybG + lw * 128, g2, b2, lane);
        {
            int np = blk * 4 + lw;
            if (np < n)
                ((float4*)(out + (size_t)np * 128))[lane] = ((float4*)(ybG + lw * 128))[lane];
        }
        // stage next x -> x1f + x8h (own row)
        if (h1) {
            ((float4*)x1fG)[lw * 32 + lane] = px;
            half2* d = (half2*)(x1hG + lw * SLH + lane * 4);
            d[0] = __floats2half2_rn(px.x, px.y);
            d[1] = __floats2half2_rn(px.z, px.w);
        }
        BARS(B4);   // x8h staged for next Q gemm
    }
}

extern "C" void kernel_launch(void* const* d_in, const int* in_sizes, int n_in,
                              void* d_out, int out_size) {
    const float* x    = (const float*)d_in[0];
    const float* knn  = (const float*)d_in[1];
    const float* xyz  = (const float*)d_in[2];
    const float* q_w  = (const float*)d_in[3];
    const float* q_b  = (const float*)d_in[4];
    const float* k_w  = (const float*)d_in[5];
    const float* k_b  = (const float*)d_in[6];
    const float* v_w  = (const float*)d_in[7];
    const float* v_b  = (const float*)d_in[8];
    const float* lw   = (const float*)d_in[9];
    const float* lb   = (const float*)d_in[10];
    const float* l1g  = (const float*)d_in[11];
    const float* l1b  = (const float*)d_in[12];
    const float* l2g  = (const float*)d_in[13];
    const float* l2b  = (const float*)d_in[14];
    float* out = (float*)d_out;
    int n = in_sizes[0] / 128;

    cudaFuncSetAttribute(tb_main, cudaFuncAttributeMaxDynamicSharedMemorySize, SMEM_TOT);
    int nsm = 148;
    cudaDeviceGetAttribute(&nsm, cudaDevAttrMultiProcessorCount, 0);

    tb_main<<<nsm, 256, SMEM_TOT>>>(x, knn, xyz, q_w, q_b, k_w, k_b, v_w, v_b,
                                    lw, lb, l1g, l1b, l2g, l2b, out, n);
}